// round 9
// baseline (speedup 1.0000x reference)
#include <cuda_runtime.h>
#include <cuda_bf16.h>

// CorrentropyLoss: cost = mean(1 - exp(-sigma * (2*(output-target))^2))
// shape (65536, 1000), sigma = 1/1000  ->  arg = 0.004 * diff^2
//
// R5: contiguous 64B-per-thread chunks (4 adjacent float4 per array per iter),
// 8 front-batched LDG.128 in flight -> better DRAM row locality + MLP.
// Fused last-block final reduction (atomic ticket, graph-replayable).

#define RED_BLOCKS 1184   // 148 SMs * 8 blocks of 256 = 2048 thr/SM
#define RED_THREADS 256

__device__ float g_partials[RED_BLOCKS];
__device__ unsigned int g_ticket;   // zero-init; reset by last block each launch

__device__ __forceinline__ float corr4(float4 a, float4 b) {
    const float C = 0.004f;  // 4 * sigma, sigma = 1/1000
    float d0 = a.x - b.x;
    float d1 = a.y - b.y;
    float d2 = a.z - b.z;
    float d3 = a.w - b.w;
    float s;
    s  = 1.0f - __expf(-C * d0 * d0);
    s += 1.0f - __expf(-C * d1 * d1);
    s += 1.0f - __expf(-C * d2 * d2);
    s += 1.0f - __expf(-C * d3 * d3);
    return s;
}

__global__ __launch_bounds__(RED_THREADS)
void corr_fused_kernel(const float4* __restrict__ o,
                       const float4* __restrict__ t,
                       int nchunk,   // n4 / 4 : chunks of 4 float4 = 64B
                       float inv_n,
                       float* __restrict__ out)
{
    float acc = 0.0f;

    int stride = gridDim.x * blockDim.x;

    for (int c = blockIdx.x * blockDim.x + threadIdx.x; c < nchunk; c += stride) {
        int base = c << 2;
        // 8 independent 16B loads front-batched (MLP_p1 = 8)
        float4 a0 = __ldcs(&o[base + 0]);
        float4 a1 = __ldcs(&o[base + 1]);
        float4 a2 = __ldcs(&o[base + 2]);
        float4 a3 = __ldcs(&o[base + 3]);
        float4 b0 = __ldcs(&t[base + 0]);
        float4 b1 = __ldcs(&t[base + 1]);
        float4 b2 = __ldcs(&t[base + 2]);
        float4 b3 = __ldcs(&t[base + 3]);
        acc += corr4(a0, b0);
        acc += corr4(a1, b1);
        acc += corr4(a2, b2);
        acc += corr4(a3, b3);
    }

    // warp reduce
    #pragma unroll
    for (int off = 16; off > 0; off >>= 1)
        acc += __shfl_xor_sync(0xffffffffu, acc, off);

    __shared__ float smem[RED_THREADS / 32];
    __shared__ bool s_is_last;
    int lane = threadIdx.x & 31;
    int wid  = threadIdx.x >> 5;
    if (lane == 0) smem[wid] = acc;
    __syncthreads();

    if (threadIdx.x == 0) {
        float s = 0.0f;
        #pragma unroll
        for (int w = 0; w < RED_THREADS / 32; w++) s += smem[w];
        g_partials[blockIdx.x] = s;
        __threadfence();
        unsigned int prev = atomicAdd(&g_ticket, 1u);
        s_is_last = (prev == (unsigned int)(gridDim.x - 1));
    }
    __syncthreads();

    if (s_is_last) {
        float facc = 0.0f;
        for (int j = threadIdx.x; j < RED_BLOCKS; j += RED_THREADS)
            facc += g_partials[j];

        #pragma unroll
        for (int off = 16; off > 0; off >>= 1)
            facc += __shfl_xor_sync(0xffffffffu, facc, off);

        if (lane == 0) smem[wid] = facc;
        __syncthreads();

        if (threadIdx.x == 0) {
            float s = 0.0f;
            #pragma unroll
            for (int w = 0; w < RED_THREADS / 32; w++) s += smem[w];
            out[0] = s * inv_n;
            g_ticket = 0;   // reset for next graph replay
        }
    }
}

extern "C" void kernel_launch(void* const* d_in, const int* in_sizes, int n_in,
                              void* d_out, int out_size)
{
    const float4* o = (const float4*)d_in[0];
    const float4* t = (const float4*)d_in[1];
    float* out = (float*)d_out;

    int n = in_sizes[0];          // 65,536,000, divisible by 16
    int nchunk = n >> 4;          // 64B chunks (4 float4)
    float inv_n = 1.0f / (float)n;

    corr_fused_kernel<<<RED_BLOCKS, RED_THREADS>>>(o, t, nchunk, inv_n, out);
}